// round 2
// baseline (speedup 1.0000x reference)
#include <cuda_runtime.h>
#include <math.h>

// Problem dims
#define BATCH   4
#define SEQ     2048
#define DMODEL  1024
#define NHEAD   16
#define DKH     64
#define ROWS    (BATCH * SEQ)          // 8192
#define LOG2E   1.4426950408889634f

// Scratch (device globals — no runtime allocation allowed)
__device__ float g_Q[(size_t)ROWS * DMODEL];
__device__ float g_K[(size_t)ROWS * DMODEL];
__device__ float g_V[(size_t)ROWS * DMODEL];
__device__ float g_CTX[(size_t)ROWS * DMODEL];

// ---------------------------------------------------------------------------
// SGEMM  C[M,N] = A[M,K] @ B[N,K]^T   (row-major, K contiguous in both: "NT")
// BM=BN=128, BK=8, 256 threads, 8x8 per thread.
// ---------------------------------------------------------------------------
__device__ __forceinline__ void sgemm_nt_128(const float* __restrict__ A,
                                             const float* __restrict__ B,
                                             float* __restrict__ C,
                                             int N, int K)
{
    __shared__ float As[8][128];
    __shared__ float Bs[8][128];

    const int tid  = threadIdx.x;
    const int brow = blockIdx.y * 128;
    const int bcol = blockIdx.x * 128;
    const int ty   = tid >> 4;          // 0..15
    const int tx   = tid & 15;          // 0..15
    const int lrow = tid >> 1;          // 0..127  (load row)
    const int lcol = (tid & 1) << 2;    // 0 or 4  (load col, float4)

    float acc[8][8];
    #pragma unroll
    for (int i = 0; i < 8; i++)
        #pragma unroll
        for (int j = 0; j < 8; j++) acc[i][j] = 0.0f;

    const float* Aptr = A + (size_t)(brow + lrow) * K + lcol;
    const float* Bptr = B + (size_t)(bcol + lrow) * K + lcol;

    for (int kk = 0; kk < K; kk += 8) {
        float4 av = *(const float4*)(Aptr + kk);
        float4 bv = *(const float4*)(Bptr + kk);
        As[lcol + 0][lrow] = av.x;  As[lcol + 1][lrow] = av.y;
        As[lcol + 2][lrow] = av.z;  As[lcol + 3][lrow] = av.w;
        Bs[lcol + 0][lrow] = bv.x;  Bs[lcol + 1][lrow] = bv.y;
        Bs[lcol + 2][lrow] = bv.z;  Bs[lcol + 3][lrow] = bv.w;
        __syncthreads();

        #pragma unroll
        for (int k = 0; k < 8; k++) {
            float4 a0 = *(const float4*)&As[k][ty * 8];
            float4 a1 = *(const float4*)&As[k][ty * 8 + 4];
            float4 b0 = *(const float4*)&Bs[k][tx * 8];
            float4 b1 = *(const float4*)&Bs[k][tx * 8 + 4];
            float ar[8] = {a0.x, a0.y, a0.z, a0.w, a1.x, a1.y, a1.z, a1.w};
            float br[8] = {b0.x, b0.y, b0.z, b0.w, b1.x, b1.y, b1.z, b1.w};
            #pragma unroll
            for (int i = 0; i < 8; i++)
                #pragma unroll
                for (int j = 0; j < 8; j++)
                    acc[i][j] = fmaf(ar[i], br[j], acc[i][j]);
        }
        __syncthreads();
    }

    #pragma unroll
    for (int i = 0; i < 8; i++) {
        float* cp = C + (size_t)(brow + ty * 8 + i) * N + bcol + tx * 8;
        *(float4*)(cp + 0) = make_float4(acc[i][0], acc[i][1], acc[i][2], acc[i][3]);
        *(float4*)(cp + 4) = make_float4(acc[i][4], acc[i][5], acc[i][6], acc[i][7]);
    }
}

// Fused Q/K/V projection: grid.z selects the weight & destination.
__global__ __launch_bounds__(256)
void sgemm_qkv(const float* __restrict__ X,
               const float* __restrict__ Wq,
               const float* __restrict__ Wk,
               const float* __restrict__ Wv)
{
    const float* W;
    float* Out;
    if (blockIdx.z == 0)      { W = Wq; Out = g_Q; }
    else if (blockIdx.z == 1) { W = Wk; Out = g_K; }
    else                      { W = Wv; Out = g_V; }
    sgemm_nt_128(X, W, Out, DMODEL, DMODEL);
}

// Output projection: out = CTX @ Wo^T
__global__ __launch_bounds__(256)
void sgemm_out(const float* __restrict__ Wo, float* __restrict__ Out)
{
    sgemm_nt_128(g_CTX, Wo, Out, DMODEL, DMODEL);
}

// ---------------------------------------------------------------------------
// Flash attention (fp32).  One block = 64 query rows of one (b, h).
// K/V streamed in 64-row tiles.  256 threads, 16x16 layout, each thread owns
// a 4x4 tile of S/P and of O.
// smem: Qs, Ks, Vs, Ps each 64 x 68 floats (padded) -> 69632 B dynamic.
// ---------------------------------------------------------------------------
#define SROW 68

extern __shared__ float att_smem[];

__global__ __launch_bounds__(256)
void attn_kernel()
{
    float* Qs = att_smem;
    float* Ks = Qs + 64 * SROW;
    float* Vs = Ks + 64 * SROW;
    float* Ps = Vs + 64 * SROW;

    const int tid = threadIdx.x;
    const int qt  = blockIdx.x;          // 0..31
    const int h   = blockIdx.y;          // 0..15
    const int b   = blockIdx.z;          // 0..3

    const size_t base = (size_t)b * SEQ * DMODEL + (size_t)h * DKH;
    const int q0 = qt * 64;

    // Load Q tile (64 x 64), row-major, padded stride
    {
        const int r  = tid >> 2;         // 0..63
        const int c4 = tid & 3;          // float4 lane
        const float* src = g_Q + base + (size_t)(q0 + r) * DMODEL;
        float* dst = Qs + r * SROW;
        #pragma unroll
        for (int j = 0; j < 4; j++) {
            int c = (c4 + j * 4) * 4;
            *(float4*)(dst + c) = *(const float4*)(src + c);
        }
    }

    const int ty = tid >> 4, tx = tid & 15;
    const int r0 = ty * 4;               // S/O row block
    const int c0 = tx * 4;               // S col block (== O dk col block)

    float o[4][4];
    float m[4], l[4];
    #pragma unroll
    for (int i = 0; i < 4; i++) {
        m[i] = -INFINITY; l[i] = 0.0f;
        #pragma unroll
        for (int j = 0; j < 4; j++) o[i][j] = 0.0f;
    }

    for (int kt = 0; kt < SEQ / 64; kt++) {
        // Load K and V tiles
        {
            const int r  = tid >> 2;
            const int c4 = tid & 3;
            const float* ksrc = g_K + base + (size_t)(kt * 64 + r) * DMODEL;
            const float* vsrc = g_V + base + (size_t)(kt * 64 + r) * DMODEL;
            float* kdst = Ks + r * SROW;
            float* vdst = Vs + r * SROW;
            #pragma unroll
            for (int j = 0; j < 4; j++) {
                int c = (c4 + j * 4) * 4;
                *(float4*)(kdst + c) = *(const float4*)(ksrc + c);
                *(float4*)(vdst + c) = *(const float4*)(vsrc + c);
            }
        }
        __syncthreads();

        // Phase 1: S = Q K^T  (4x4 per thread over DK=64)
        float s[4][4];
        #pragma unroll
        for (int i = 0; i < 4; i++)
            #pragma unroll
            for (int j = 0; j < 4; j++) s[i][j] = 0.0f;

        #pragma unroll
        for (int d = 0; d < DKH; d += 4) {
            float4 qv[4], kv[4];
            #pragma unroll
            for (int i = 0; i < 4; i++) qv[i] = *(const float4*)(Qs + (r0 + i) * SROW + d);
            #pragma unroll
            for (int j = 0; j < 4; j++) kv[j] = *(const float4*)(Ks + (c0 + j) * SROW + d);
            #pragma unroll
            for (int i = 0; i < 4; i++)
                #pragma unroll
                for (int j = 0; j < 4; j++) {
                    s[i][j] = fmaf(qv[i].x, kv[j].x, s[i][j]);
                    s[i][j] = fmaf(qv[i].y, kv[j].y, s[i][j]);
                    s[i][j] = fmaf(qv[i].z, kv[j].z, s[i][j]);
                    s[i][j] = fmaf(qv[i].w, kv[j].w, s[i][j]);
                }
        }

        // Online softmax per row (reduce across the 16 tx lanes; lanes with
        // the same ty sit in one 16-lane half-warp, so xor masks 1/2/4/8 work)
        #pragma unroll
        for (int i = 0; i < 4; i++) {
            #pragma unroll
            for (int j = 0; j < 4; j++) s[i][j] *= 0.125f;   // 1/sqrt(64)

            float mx = fmaxf(fmaxf(s[i][0], s[i][1]), fmaxf(s[i][2], s[i][3]));
            #pragma unroll
            for (int off = 8; off >= 1; off >>= 1)
                mx = fmaxf(mx, __shfl_xor_sync(0xffffffffu, mx, off));

            float mnew = fmaxf(m[i], mx);
            float corr = exp2f((m[i] - mnew) * LOG2E);
            m[i] = mnew;

            float rs = 0.0f;
            #pragma unroll
            for (int j = 0; j < 4; j++) {
                s[i][j] = exp2f((s[i][j] - mnew) * LOG2E);
                rs += s[i][j];
            }
            #pragma unroll
            for (int off = 8; off >= 1; off >>= 1)
                rs += __shfl_xor_sync(0xffffffffu, rs, off);

            l[i] = l[i] * corr + rs;
            #pragma unroll
            for (int j = 0; j < 4; j++) o[i][j] *= corr;

            *(float4*)(Ps + (r0 + i) * SROW + c0) =
                make_float4(s[i][0], s[i][1], s[i][2], s[i][3]);
        }
        __syncthreads();

        // Phase 2: O += P @ V   (rows r0.., dk-cols c0..)
        #pragma unroll 4
        for (int k = 0; k < 64; k += 4) {
            float p[4][4];
            #pragma unroll
            for (int i = 0; i < 4; i++) {
                float4 pv = *(const float4*)(Ps + (r0 + i) * SROW + k);
                p[i][0] = pv.x; p[i][1] = pv.y; p[i][2] = pv.z; p[i][3] = pv.w;
            }
            #pragma unroll
            for (int kk = 0; kk < 4; kk++) {
                float4 vv = *(const float4*)(Vs + (k + kk) * SROW + c0);
                #pragma unroll
                for (int i = 0; i < 4; i++) {
                    o[i][0] = fmaf(p[i][kk], vv.x, o[i][0]);
                    o[i][1] = fmaf(p[i][kk], vv.y, o[i][1]);
                    o[i][2] = fmaf(p[i][kk], vv.z, o[i][2]);
                    o[i][3] = fmaf(p[i][kk], vv.w, o[i][3]);
                }
            }
        }
        __syncthreads();
    }

    // Finalize: divide by l, write ctx
    #pragma unroll
    for (int i = 0; i < 4; i++) {
        float inv = 1.0f / l[i];
        float* dst = g_CTX + base + (size_t)(q0 + r0 + i) * DMODEL + c0;
        *(float4*)dst = make_float4(o[i][0] * inv, o[i][1] * inv,
                                    o[i][2] * inv, o[i][3] * inv);
    }
}

// ---------------------------------------------------------------------------
extern "C" void kernel_launch(void* const* d_in, const int* in_sizes, int n_in,
                              void* d_out, int out_size)
{
    (void)in_sizes; (void)n_in; (void)out_size;
    const float* emb = (const float*)d_in[0];
    const float* Wq  = (const float*)d_in[1];
    const float* Wk  = (const float*)d_in[2];
    const float* Wv  = (const float*)d_in[3];
    const float* Wo  = (const float*)d_in[4];
    float* out = (float*)d_out;

    // QKV projections (fused grid over z)
    dim3 g1(DMODEL / 128, ROWS / 128, 3);
    sgemm_qkv<<<g1, 256>>>(emb, Wq, Wk, Wv);

    // Flash attention
    const int att_smem_bytes = 4 * 64 * SROW * (int)sizeof(float);   // 69632
    cudaFuncSetAttribute(attn_kernel,
                         cudaFuncAttributeMaxDynamicSharedMemorySize,
                         att_smem_bytes);
    dim3 g2(SEQ / 64, NHEAD, BATCH);
    attn_kernel<<<g2, 256, att_smem_bytes>>>();

    // Output projection
    dim3 g3(DMODEL / 128, ROWS / 128, 1);
    sgemm_out<<<g3, 256>>>(Wo, out);
}

// round 5
// speedup vs baseline: 1.3053x; 1.3053x over previous
#include <cuda_runtime.h>
#include <cuda_bf16.h>
#include <math.h>
#include <stdint.h>

// Problem dims
#define BATCH   4
#define SEQ     2048
#define DMODEL  1024
#define NHEAD   16
#define DKH     64
#define ROWS    (BATCH * SEQ)          // 8192
#define LOG2E   1.4426950408889634f

// ---------------------------------------------------------------------------
// Device scratch (no runtime allocation allowed)
// ---------------------------------------------------------------------------
__device__ float g_Q[(size_t)ROWS * DMODEL];
__device__ float g_K[(size_t)ROWS * DMODEL];
__device__ float g_V[(size_t)ROWS * DMODEL];

__device__ __nv_bfloat16 g_Xh[(size_t)ROWS * DMODEL];
__device__ __nv_bfloat16 g_Xl[(size_t)ROWS * DMODEL];
__device__ __nv_bfloat16 g_Ch[(size_t)ROWS * DMODEL];
__device__ __nv_bfloat16 g_Cl[(size_t)ROWS * DMODEL];

__device__ __nv_bfloat16 g_Wqh[DMODEL * DMODEL], g_Wql[DMODEL * DMODEL];
__device__ __nv_bfloat16 g_Wkh[DMODEL * DMODEL], g_Wkl[DMODEL * DMODEL];
__device__ __nv_bfloat16 g_Wvh[DMODEL * DMODEL], g_Wvl[DMODEL * DMODEL];
__device__ __nv_bfloat16 g_Woh[DMODEL * DMODEL], g_Wol[DMODEL * DMODEL];

// ---------------------------------------------------------------------------
// Portable tensor-core helpers (sm_80+ ISA: mma.sync / ldmatrix / cp.async)
// ---------------------------------------------------------------------------
__device__ __forceinline__ uint32_t smem_to_u32(const void* smem_ptr) {
    uint32_t addr;
    asm("{ .reg .u64 tmp; cvta.to.shared.u64 tmp, %1; cvt.u32.u64 %0, tmp; }"
        : "=r"(addr) : "l"(smem_ptr));
    return addr;
}

__device__ __forceinline__ void cp_async16(uint32_t saddr, const void* gptr) {
    asm volatile("cp.async.cg.shared.global [%0], [%1], 16;"
                 :: "r"(saddr), "l"(gptr) : "memory");
}
__device__ __forceinline__ void cp_commit() {
    asm volatile("cp.async.commit_group;" ::: "memory");
}
__device__ __forceinline__ void cp_wait0() {
    asm volatile("cp.async.wait_group 0;" ::: "memory");
}

__device__ __forceinline__ void ldsm_x4(uint32_t* r, uint32_t addr) {
    asm volatile("ldmatrix.sync.aligned.m8n8.x4.shared.b16 {%0,%1,%2,%3}, [%4];"
                 : "=r"(r[0]), "=r"(r[1]), "=r"(r[2]), "=r"(r[3])
                 : "r"(addr));
}

__device__ __forceinline__ void mma16816(float* c, const uint32_t* a,
                                         const uint32_t* b) {
    asm volatile(
        "mma.sync.aligned.m16n8k16.row.col.f32.bf16.bf16.f32 "
        "{%0,%1,%2,%3}, {%4,%5,%6,%7}, {%8,%9}, {%0,%1,%2,%3};"
        : "+f"(c[0]), "+f"(c[1]), "+f"(c[2]), "+f"(c[3])
        : "r"(a[0]), "r"(a[1]), "r"(a[2]), "r"(a[3]),
          "r"(b[0]), "r"(b[1]));
}

// ---------------------------------------------------------------------------
// Split fp32 -> (hi, lo) bf16 pair.  x = hi + lo + O(2^-18 x)
// ---------------------------------------------------------------------------
__global__ __launch_bounds__(256)
void split_all(const float* __restrict__ emb,
               const float* __restrict__ Wq, const float* __restrict__ Wk,
               const float* __restrict__ Wv, const float* __restrict__ Wo)
{
    const float* src;
    __nv_bfloat16 *hi, *lo;
    int n4;
    switch (blockIdx.z) {
        case 0: src = emb; hi = g_Xh;  lo = g_Xl;  n4 = ROWS * DMODEL / 4;   break;
        case 1: src = Wq;  hi = g_Wqh; lo = g_Wql; n4 = DMODEL * DMODEL / 4; break;
        case 2: src = Wk;  hi = g_Wkh; lo = g_Wkl; n4 = DMODEL * DMODEL / 4; break;
        case 3: src = Wv;  hi = g_Wvh; lo = g_Wvl; n4 = DMODEL * DMODEL / 4; break;
        default: src = Wo; hi = g_Woh; lo = g_Wol; n4 = DMODEL * DMODEL / 4; break;
    }
    int i = blockIdx.x * 256 + threadIdx.x;
    if (i >= n4) return;
    float4 f = ((const float4*)src)[i];
    __nv_bfloat16 h0 = __float2bfloat16(f.x);
    __nv_bfloat16 h1 = __float2bfloat16(f.y);
    __nv_bfloat16 h2 = __float2bfloat16(f.z);
    __nv_bfloat16 h3 = __float2bfloat16(f.w);
    __nv_bfloat16 l0 = __float2bfloat16(f.x - __bfloat162float(h0));
    __nv_bfloat16 l1 = __float2bfloat16(f.y - __bfloat162float(h1));
    __nv_bfloat16 l2 = __float2bfloat16(f.z - __bfloat162float(h2));
    __nv_bfloat16 l3 = __float2bfloat16(f.w - __bfloat162float(h3));
    __nv_bfloat162* hp = (__nv_bfloat162*)(hi + (size_t)i * 4);
    __nv_bfloat162* lp = (__nv_bfloat162*)(lo + (size_t)i * 4);
    hp[0] = __nv_bfloat162{h0, h1};  hp[1] = __nv_bfloat162{h2, h3};
    lp[0] = __nv_bfloat162{l0, l1};  lp[1] = __nv_bfloat162{l2, l3};
}

// ---------------------------------------------------------------------------
// Split-bf16 HMMA GEMM: C[M,Ntot] = A[M,K] @ B[N,K]^T  (both K-major)
// CTA 128x128, BK=32, 8 warps (4x2), warp tile 32x64 (2 m16 x 8 n8).
// Terms: AhBh + AlBh + AhBl accumulate in fp32 regs.
// smem: 2 stages x 4 tiles x (128 x LDA bf16).
// ---------------------------------------------------------------------------
#define BK     32
#define LDA    40                       // padded row stride (bf16 elems)
#define TILE_B (128 * LDA * 2)          // 10240 B
#define ST_AH  0
#define ST_AL  (1 * TILE_B)
#define ST_BH  (2 * TILE_B)
#define ST_BL  (3 * TILE_B)
#define STAGE_B (4 * TILE_B)            // 40960 B
#define GS_TOTAL (2 * STAGE_B)          // 81920 B

__device__ __forceinline__ void gemm_bf16split(
    const __nv_bfloat16* __restrict__ Ah, const __nv_bfloat16* __restrict__ Al,
    const __nv_bfloat16* __restrict__ Bh, const __nv_bfloat16* __restrict__ Bl,
    float* __restrict__ C, int Ntot, int K)
{
    extern __shared__ char gs[];
    const uint32_t sb = smem_to_u32(gs);
    const int tid  = threadIdx.x;
    const int wid  = tid >> 5;
    const int lane = tid & 31;
    const int wm = wid >> 1;            // 0..3 -> 32-row slab
    const int wn = wid & 1;             // 0..1 -> 64-col slab
    const int m0 = blockIdx.y * 128;
    const int n0 = blockIdx.x * 128;

    // Loader mapping: 2 threads per 32-elem row, 16 bf16 (32B = 2x16B) each
    const int lrow = tid >> 1;
    const int lseg = (tid & 1) * 16;
    const __nv_bfloat16* aHp = Ah + (size_t)(m0 + lrow) * K + lseg;
    const __nv_bfloat16* aLp = Al + (size_t)(m0 + lrow) * K + lseg;
    const __nv_bfloat16* bHp = Bh + (size_t)(n0 + lrow) * K + lseg;
    const __nv_bfloat16* bLp = Bl + (size_t)(n0 + lrow) * K + lseg;
    const uint32_t sto = (uint32_t)(lrow * LDA + lseg) * 2;

    float acc[2][8][4];
    #pragma unroll
    for (int t = 0; t < 2; t++)
        #pragma unroll
        for (int nt = 0; nt < 8; nt++)
            #pragma unroll
            for (int j = 0; j < 4; j++) acc[t][nt][j] = 0.0f;

    // ldmatrix lane addressing
    const int a_row  = (lane & 15);             // + wm*32 + t*16
    const int a_koff = (lane & 16) >> 1;        // 0 or 8 elems
    const int b_row  = ((lane & 16) >> 1) + (lane & 7);  // + wn*64 + np*16
    const int b_koff = (lane & 8);

    const uint32_t aBase = sb + (uint32_t)((wm * 32 + a_row) * LDA + a_koff) * 2;
    const uint32_t bBase = sb + (uint32_t)((wn * 64 + b_row) * LDA + b_koff) * 2;

    int st = 0;
    // Prologue: stage 0  (each thread: 32B = chunks at +0 and +16)
    {
        uint32_t d = sb + sto;
        cp_async16(d + ST_AH, aHp);       cp_async16(d + ST_AH + 16, (const char*)aHp + 16);
        cp_async16(d + ST_AL, aLp);       cp_async16(d + ST_AL + 16, (const char*)aLp + 16);
        cp_async16(d + ST_BH, bHp);       cp_async16(d + ST_BH + 16, (const char*)bHp + 16);
        cp_async16(d + ST_BL, bLp);       cp_async16(d + ST_BL + 16, (const char*)bLp + 16);
        cp_commit();
    }

    for (int kb = 0; kb < K; kb += BK) {
        cp_wait0();
        __syncthreads();

        // Prefetch next stage
        if (kb + BK < K) {
            uint32_t d = sb + (st ^ 1) * STAGE_B + sto;
            const int ko = kb + BK;
            cp_async16(d + ST_AH, aHp + ko);  cp_async16(d + ST_AH + 16, (const char*)(aHp + ko) + 16);
            cp_async16(d + ST_AL, aLp + ko);  cp_async16(d + ST_AL + 16, (const char*)(aLp + ko) + 16);
            cp_async16(d + ST_BH, bHp + ko);  cp_async16(d + ST_BH + 16, (const char*)(bHp + ko) + 16);
            cp_async16(d + ST_BL, bLp + ko);  cp_async16(d + ST_BL + 16, (const char*)(bLp + ko) + 16);
            cp_commit();
        }

        const uint32_t stb = (uint32_t)(st * STAGE_B);
        #pragma unroll
        for (int ks = 0; ks < 2; ks++) {
            const uint32_t kb2 = (uint32_t)(ks * 16) * 2;
            uint32_t aH[2][4], aL[2][4], b[4][4];
            #pragma unroll
            for (int t = 0; t < 2; t++) {
                ldsm_x4(aH[t], aBase + stb + ST_AH + (uint32_t)(t * 16 * LDA) * 2 + kb2);
                ldsm_x4(aL[t], aBase + stb + ST_AL + (uint32_t)(t * 16 * LDA) * 2 + kb2);
            }
            // Bh: AhBh + AlBh
            #pragma unroll
            for (int np = 0; np < 4; np++)
                ldsm_x4(b[np], bBase + stb + ST_BH + (uint32_t)(np * 16 * LDA) * 2 + kb2);
            #pragma unroll
            for (int t = 0; t < 2; t++)
                #pragma unroll
                for (int nt = 0; nt < 8; nt++) {
                    mma16816(acc[t][nt], aH[t], &b[nt >> 1][(nt & 1) * 2]);
                }
            #pragma unroll
            for (int t = 0; t < 2; t++)
                #pragma unroll
                for (int nt = 0; nt < 8; nt++) {
                    mma16816(acc[t][nt], aL[t], &b[nt >> 1][(nt & 1) * 2]);
                }
            // Bl: AhBl
            #pragma unroll
            for (int np = 0; np < 4; np++)
                ldsm_x4(b[np], bBase + stb + ST_BL + (uint32_t)(np * 16 * LDA) * 2 + kb2);
            #pragma unroll
            for (int t = 0; t < 2; t++)
                #pragma unroll
                for (int nt = 0; nt < 8; nt++) {
                    mma16816(acc[t][nt], aH[t], &b[nt >> 1][(nt & 1) * 2]);
                }
        }
        st ^= 1;
        __syncthreads();
    }

    // Epilogue
    const int g = lane >> 2, tig = lane & 3;
    #pragma unroll
    for (int t = 0; t < 2; t++) {
        const int row = m0 + wm * 32 + t * 16 + g;
        #pragma unroll
        for (int nt = 0; nt < 8; nt++) {
            const int col = n0 + wn * 64 + nt * 8 + tig * 2;
            *(float2*)(C + (size_t)row * Ntot + col) =
                make_float2(acc[t][nt][0], acc[t][nt][1]);
            *(float2*)(C + (size_t)(row + 8) * Ntot + col) =
                make_float2(acc[t][nt][2], acc[t][nt][3]);
        }
    }
}

__global__ __launch_bounds__(256)
void qkv_mma()
{
    const __nv_bfloat16 *Bh, *Bl;
    float* Out;
    if (blockIdx.z == 0)      { Bh = g_Wqh; Bl = g_Wql; Out = g_Q; }
    else if (blockIdx.z == 1) { Bh = g_Wkh; Bl = g_Wkl; Out = g_K; }
    else                      { Bh = g_Wvh; Bl = g_Wvl; Out = g_V; }
    gemm_bf16split(g_Xh, g_Xl, Bh, Bl, Out, DMODEL, DMODEL);
}

__global__ __launch_bounds__(256)
void out_mma(float* __restrict__ Out)
{
    gemm_bf16split(g_Ch, g_Cl, g_Woh, g_Wol, Out, DMODEL, DMODEL);
}

// ---------------------------------------------------------------------------
// Flash attention (fp32).  Epilogue writes split-bf16 ctx for the out-proj.
// ---------------------------------------------------------------------------
#define SROW 68

extern __shared__ float att_smem[];

__global__ __launch_bounds__(256)
void attn_kernel()
{
    float* Qs = att_smem;
    float* Ks = Qs + 64 * SROW;
    float* Vs = Ks + 64 * SROW;
    float* Ps = Vs + 64 * SROW;

    const int tid = threadIdx.x;
    const int qt  = blockIdx.x;
    const int h   = blockIdx.y;
    const int b   = blockIdx.z;

    const size_t base = (size_t)b * SEQ * DMODEL + (size_t)h * DKH;
    const int q0 = qt * 64;

    {
        const int r  = tid >> 2;
        const int c4 = tid & 3;
        const float* src = g_Q + base + (size_t)(q0 + r) * DMODEL;
        float* dst = Qs + r * SROW;
        #pragma unroll
        for (int j = 0; j < 4; j++) {
            int c = (c4 + j * 4) * 4;
            *(float4*)(dst + c) = *(const float4*)(src + c);
        }
    }

    const int ty = tid >> 4, tx = tid & 15;
    const int r0 = ty * 4;
    const int c0 = tx * 4;

    float o[4][4];
    float m[4], l[4];
    #pragma unroll
    for (int i = 0; i < 4; i++) {
        m[i] = -INFINITY; l[i] = 0.0f;
        #pragma unroll
        for (int j = 0; j < 4; j++) o[i][j] = 0.0f;
    }

    for (int kt = 0; kt < SEQ / 64; kt++) {
        {
            const int r  = tid >> 2;
            const int c4 = tid & 3;
            const float* ksrc = g_K + base + (size_t)(kt * 64 + r) * DMODEL;
            const float* vsrc = g_V + base + (size_t)(kt * 64 + r) * DMODEL;
            float* kdst = Ks + r * SROW;
            float* vdst = Vs + r * SROW;
            #pragma unroll
            for (int j = 0; j < 4; j++) {
                int c = (c4 + j * 4) * 4;
                *(float4*)(kdst + c) = *(const float4*)(ksrc + c);
                *(float4*)(vdst + c) = *(const float4*)(vsrc + c);
            }
        }
        __syncthreads();

        float s[4][4];
        #pragma unroll
        for (int i = 0; i < 4; i++)
            #pragma unroll
            for (int j = 0; j < 4; j++) s[i][j] = 0.0f;

        #pragma unroll
        for (int d = 0; d < DKH; d += 4) {
            float4 qv[4], kv[4];
            #pragma unroll
            for (int i = 0; i < 4; i++) qv[i] = *(const float4*)(Qs + (r0 + i) * SROW + d);
            #pragma unroll
            for (int j = 0; j < 4; j++) kv[j] = *(const float4*)(Ks + (c0 + j) * SROW + d);
            #pragma unroll
            for (int i = 0; i < 4; i++)
                #pragma unroll
                for (int j = 0; j < 4; j++) {
                    s[i][j] = fmaf(qv[i].x, kv[j].x, s[i][j]);
                    s[i][j] = fmaf(qv[i].y, kv[j].y, s[i][j]);
                    s[i][j] = fmaf(qv[i].z, kv[j].z, s[i][j]);
                    s[i][j] = fmaf(qv[i].w, kv[j].w, s[i][j]);
                }
        }

        #pragma unroll
        for (int i = 0; i < 4; i++) {
            #pragma unroll
            for (int j = 0; j < 4; j++) s[i][j] *= 0.125f;

            float mx = fmaxf(fmaxf(s[i][0], s[i][1]), fmaxf(s[i][2], s[i][3]));
            #pragma unroll
            for (int off = 8; off >= 1; off >>= 1)
                mx = fmaxf(mx, __shfl_xor_sync(0xffffffffu, mx, off));

            float mnew = fmaxf(m[i], mx);
            float corr = exp2f((m[i] - mnew) * LOG2E);
            m[i] = mnew;

            float rs = 0.0f;
            #pragma unroll
            for (int j = 0; j < 4; j++) {
                s[i][j] = exp2f((s[i][j] - mnew) * LOG2E);
                rs += s[i][j];
            }
            #pragma unroll
            for (int off = 8; off >= 1; off >>= 1)
                rs += __shfl_xor_sync(0xffffffffu, rs, off);

            l[i] = l[i] * corr + rs;
            #pragma unroll
            for (int j = 0; j < 4; j++) o[i][j] *= corr;

            *(float4*)(Ps + (r0 + i) * SROW + c0) =
                make_float4(s[i][0], s[i][1], s[i][2], s[i][3]);
        }
        __syncthreads();

        #pragma unroll 4
        for (int k = 0; k < 64; k += 4) {
            float p[4][4];
            #pragma unroll
            for (int i = 0; i < 4; i++) {
                float4 pv = *(const float4*)(Ps + (r0 + i) * SROW + k);
                p[i][0] = pv.x; p[i][1] = pv.y; p[i][2] = pv.z; p[i][3] = pv.w;
            }
            #pragma unroll
            for (int kk = 0; kk < 4; kk++) {
                float4 vv = *(const float4*)(Vs + (k + kk) * SROW + c0);
                #pragma unroll
                for (int i = 0; i < 4; i++) {
                    o[i][0] = fmaf(p[i][kk], vv.x, o[i][0]);
                    o[i][1] = fmaf(p[i][kk], vv.y, o[i][1]);
                    o[i][2] = fmaf(p[i][kk], vv.z, o[i][2]);
                    o[i][3] = fmaf(p[i][kk], vv.w, o[i][3]);
                }
            }
        }
        __syncthreads();
    }

    // Finalize: normalize, write split-bf16 ctx
    #pragma unroll
    for (int i = 0; i < 4; i++) {
        float inv = 1.0f / l[i];
        size_t idx = base + (size_t)(q0 + r0 + i) * DMODEL + c0;
        float v0 = o[i][0] * inv, v1 = o[i][1] * inv;
        float v2 = o[i][2] * inv, v3 = o[i][3] * inv;
        __nv_bfloat16 h0 = __float2bfloat16(v0);
        __nv_bfloat16 h1 = __float2bfloat16(v1);
        __nv_bfloat16 h2 = __float2bfloat16(v2);
        __nv_bfloat16 h3 = __float2bfloat16(v3);
        __nv_bfloat16 l0 = __float2bfloat16(v0 - __bfloat162float(h0));
        __nv_bfloat16 l1 = __float2bfloat16(v1 - __bfloat162float(h1));
        __nv_bfloat16 l2 = __float2bfloat16(v2 - __bfloat162float(h2));
        __nv_bfloat16 l3 = __float2bfloat16(v3 - __bfloat162float(h3));
        __nv_bfloat162* hp = (__nv_bfloat162*)(g_Ch + idx);
        __nv_bfloat162* lp = (__nv_bfloat162*)(g_Cl + idx);
        hp[0] = __nv_bfloat162{h0, h1};  hp[1] = __nv_bfloat162{h2, h3};
        lp[0] = __nv_bfloat162{l0, l1};  lp[1] = __nv_bfloat162{l2, l3};
    }
}

// ---------------------------------------------------------------------------
extern "C" void kernel_launch(void* const* d_in, const int* in_sizes, int n_in,
                              void* d_out, int out_size)
{
    (void)in_sizes; (void)n_in; (void)out_size;
    const float* emb = (const float*)d_in[0];
    const float* Wq  = (const float*)d_in[1];
    const float* Wk  = (const float*)d_in[2];
    const float* Wv  = (const float*)d_in[3];
    const float* Wo  = (const float*)d_in[4];
    float* out = (float*)d_out;

    // 1. Split fp32 -> bf16 hi/lo
    dim3 gsplit(ROWS * DMODEL / 4 / 256, 1, 5);
    split_all<<<gsplit, 256>>>(emb, Wq, Wk, Wv, Wo);

    // 2. QKV projections (HMMA split-bf16)
    cudaFuncSetAttribute(qkv_mma, cudaFuncAttributeMaxDynamicSharedMemorySize,
                         GS_TOTAL);
    dim3 g1(DMODEL / 128, ROWS / 128, 3);
    qkv_mma<<<g1, 256, GS_TOTAL>>>();

    // 3. Flash attention (fp32), writes split-bf16 ctx
    const int att_smem_bytes = 4 * 64 * SROW * (int)sizeof(float);
    cudaFuncSetAttribute(attn_kernel,
                         cudaFuncAttributeMaxDynamicSharedMemorySize,
                         att_smem_bytes);
    dim3 g2(SEQ / 64, NHEAD, BATCH);
    attn_kernel<<<g2, 256, att_smem_bytes>>>();

    // 4. Output projection (HMMA split-bf16)
    cudaFuncSetAttribute(out_mma, cudaFuncAttributeMaxDynamicSharedMemorySize,
                         GS_TOTAL);
    dim3 g3(DMODEL / 128, ROWS / 128, 1);
    out_mma<<<g3, 256, GS_TOTAL>>>(out);
}

// round 6
// speedup vs baseline: 3.4610x; 2.6515x over previous
#include <cuda_runtime.h>
#include <cuda_bf16.h>
#include <math.h>
#include <stdint.h>

// Problem dims
#define BATCH   4
#define SEQ     2048
#define DMODEL  1024
#define NHEAD   16
#define DKH     64
#define ROWS    (BATCH * SEQ)          // 8192
#define SL      0.1803368801111204f    // log2(e)/8  (1/sqrt(64) folded in)

// ---------------------------------------------------------------------------
// Device scratch
// ---------------------------------------------------------------------------
__device__ __nv_bfloat16 g_Xh[(size_t)ROWS * DMODEL];
__device__ __nv_bfloat16 g_Xl[(size_t)ROWS * DMODEL];
__device__ __nv_bfloat16 g_Qh[(size_t)ROWS * DMODEL];
__device__ __nv_bfloat16 g_Ql[(size_t)ROWS * DMODEL];
__device__ __nv_bfloat16 g_Kh[(size_t)ROWS * DMODEL];
__device__ __nv_bfloat16 g_Kl[(size_t)ROWS * DMODEL];
__device__ __nv_bfloat16 g_Vh[(size_t)ROWS * DMODEL];
__device__ __nv_bfloat16 g_Vl[(size_t)ROWS * DMODEL];
__device__ __nv_bfloat16 g_Ch[(size_t)ROWS * DMODEL];
__device__ __nv_bfloat16 g_Cl[(size_t)ROWS * DMODEL];

__device__ __nv_bfloat16 g_Wqh[DMODEL * DMODEL], g_Wql[DMODEL * DMODEL];
__device__ __nv_bfloat16 g_Wkh[DMODEL * DMODEL], g_Wkl[DMODEL * DMODEL];
__device__ __nv_bfloat16 g_Wvh[DMODEL * DMODEL], g_Wvl[DMODEL * DMODEL];
__device__ __nv_bfloat16 g_Woh[DMODEL * DMODEL], g_Wol[DMODEL * DMODEL];

// ---------------------------------------------------------------------------
// Helpers (sm_80+ portable ISA)
// ---------------------------------------------------------------------------
__device__ __forceinline__ uint32_t smem_to_u32(const void* p) {
    uint32_t a;
    asm("{ .reg .u64 tmp; cvta.to.shared.u64 tmp, %1; cvt.u32.u64 %0, tmp; }"
        : "=r"(a) : "l"(p));
    return a;
}
__device__ __forceinline__ void cp_async16(uint32_t s, const void* g) {
    asm volatile("cp.async.cg.shared.global [%0], [%1], 16;" :: "r"(s), "l"(g) : "memory");
}
__device__ __forceinline__ void cp_commit() { asm volatile("cp.async.commit_group;" ::: "memory"); }
__device__ __forceinline__ void cp_wait0()  { asm volatile("cp.async.wait_group 0;" ::: "memory"); }

__device__ __forceinline__ void ldsm_x4(uint32_t* r, uint32_t a) {
    asm volatile("ldmatrix.sync.aligned.m8n8.x4.shared.b16 {%0,%1,%2,%3}, [%4];"
                 : "=r"(r[0]), "=r"(r[1]), "=r"(r[2]), "=r"(r[3]) : "r"(a));
}
__device__ __forceinline__ void ldsm_x4t(uint32_t* r, uint32_t a) {
    asm volatile("ldmatrix.sync.aligned.m8n8.x4.trans.shared.b16 {%0,%1,%2,%3}, [%4];"
                 : "=r"(r[0]), "=r"(r[1]), "=r"(r[2]), "=r"(r[3]) : "r"(a));
}
__device__ __forceinline__ void mma16816(float* c, const uint32_t* a, const uint32_t* b) {
    asm volatile(
        "mma.sync.aligned.m16n8k16.row.col.f32.bf16.bf16.f32 "
        "{%0,%1,%2,%3}, {%4,%5,%6,%7}, {%8,%9}, {%0,%1,%2,%3};"
        : "+f"(c[0]), "+f"(c[1]), "+f"(c[2]), "+f"(c[3])
        : "r"(a[0]), "r"(a[1]), "r"(a[2]), "r"(a[3]), "r"(b[0]), "r"(b[1]));
}
__device__ __forceinline__ float ex2f(float x) {
    float y; asm("ex2.approx.f32 %0, %1;" : "=f"(y) : "f"(x)); return y;
}
// pack {lo=a, hi=b} as bf16x2
__device__ __forceinline__ uint32_t hpack2(float a, float b) {
    uint32_t r; asm("cvt.rn.bf16x2.f32 %0, %1, %2;" : "=r"(r) : "f"(b), "f"(a)); return r;
}
// split pair (a,b) into hi-pair + lo-pair bf16x2
__device__ __forceinline__ void split2(float a, float b, uint32_t& hp, uint32_t& lp) {
    hp = hpack2(a, b);
    float ha = __uint_as_float(hp << 16);
    float hb = __uint_as_float(hp & 0xffff0000u);
    lp = hpack2(a - ha, b - hb);
}

// ---------------------------------------------------------------------------
// Split fp32 -> (hi, lo) bf16
// ---------------------------------------------------------------------------
__global__ __launch_bounds__(256)
void split_all(const float* __restrict__ emb,
               const float* __restrict__ Wq, const float* __restrict__ Wk,
               const float* __restrict__ Wv, const float* __restrict__ Wo)
{
    const float* src;
    __nv_bfloat16 *hi, *lo;
    int n4;
    switch (blockIdx.z) {
        case 0: src = emb; hi = g_Xh;  lo = g_Xl;  n4 = ROWS * DMODEL / 4;   break;
        case 1: src = Wq;  hi = g_Wqh; lo = g_Wql; n4 = DMODEL * DMODEL / 4; break;
        case 2: src = Wk;  hi = g_Wkh; lo = g_Wkl; n4 = DMODEL * DMODEL / 4; break;
        case 3: src = Wv;  hi = g_Wvh; lo = g_Wvl; n4 = DMODEL * DMODEL / 4; break;
        default: src = Wo; hi = g_Woh; lo = g_Wol; n4 = DMODEL * DMODEL / 4; break;
    }
    int i = blockIdx.x * 256 + threadIdx.x;
    if (i >= n4) return;
    float4 f = ((const float4*)src)[i];
    uint32_t h0, l0, h1, l1;
    split2(f.x, f.y, h0, l0);
    split2(f.z, f.w, h1, l1);
    uint32_t* hp = (uint32_t*)(hi + (size_t)i * 4);
    uint32_t* lp = (uint32_t*)(lo + (size_t)i * 4);
    hp[0] = h0; hp[1] = h1;
    lp[0] = l0; lp[1] = l1;
}

// ---------------------------------------------------------------------------
// Split-bf16 HMMA GEMM: C = A[M,K] @ B[N,K]^T.  Output fp32 or split-bf16.
// ---------------------------------------------------------------------------
#define BK     32
#define LDA    40
#define TILE_B (128 * LDA * 2)
#define ST_AH  0
#define ST_AL  (1 * TILE_B)
#define ST_BH  (2 * TILE_B)
#define ST_BL  (3 * TILE_B)
#define STAGE_B (4 * TILE_B)
#define GS_TOTAL (2 * STAGE_B)

template <bool SPLIT_OUT>
__device__ __forceinline__ void gemm_bf16split(
    const __nv_bfloat16* __restrict__ Ah, const __nv_bfloat16* __restrict__ Al,
    const __nv_bfloat16* __restrict__ Bh, const __nv_bfloat16* __restrict__ Bl,
    float* __restrict__ C, __nv_bfloat16* __restrict__ Chi,
    __nv_bfloat16* __restrict__ Clo, int Ntot, int K)
{
    extern __shared__ char gs[];
    const uint32_t sb = smem_to_u32(gs);
    const int tid  = threadIdx.x;
    const int wid  = tid >> 5;
    const int lane = tid & 31;
    const int wm = wid >> 1;
    const int wn = wid & 1;
    const int m0 = blockIdx.y * 128;
    const int n0 = blockIdx.x * 128;

    const int lrow = tid >> 1;
    const int lseg = (tid & 1) * 16;
    const __nv_bfloat16* aHp = Ah + (size_t)(m0 + lrow) * K + lseg;
    const __nv_bfloat16* aLp = Al + (size_t)(m0 + lrow) * K + lseg;
    const __nv_bfloat16* bHp = Bh + (size_t)(n0 + lrow) * K + lseg;
    const __nv_bfloat16* bLp = Bl + (size_t)(n0 + lrow) * K + lseg;
    const uint32_t sto = (uint32_t)(lrow * LDA + lseg) * 2;

    float acc[2][8][4];
    #pragma unroll
    for (int t = 0; t < 2; t++)
        #pragma unroll
        for (int nt = 0; nt < 8; nt++)
            #pragma unroll
            for (int j = 0; j < 4; j++) acc[t][nt][j] = 0.0f;

    const int a_row  = (lane & 15);
    const int a_koff = (lane & 16) >> 1;
    const int b_row  = ((lane & 16) >> 1) + (lane & 7);
    const int b_koff = (lane & 8);

    const uint32_t aBase = sb + (uint32_t)((wm * 32 + a_row) * LDA + a_koff) * 2;
    const uint32_t bBase = sb + (uint32_t)((wn * 64 + b_row) * LDA + b_koff) * 2;

    int st = 0;
    {
        uint32_t d = sb + sto;
        cp_async16(d + ST_AH, aHp);  cp_async16(d + ST_AH + 16, (const char*)aHp + 16);
        cp_async16(d + ST_AL, aLp);  cp_async16(d + ST_AL + 16, (const char*)aLp + 16);
        cp_async16(d + ST_BH, bHp);  cp_async16(d + ST_BH + 16, (const char*)bHp + 16);
        cp_async16(d + ST_BL, bLp);  cp_async16(d + ST_BL + 16, (const char*)bLp + 16);
        cp_commit();
    }

    for (int kb = 0; kb < K; kb += BK) {
        cp_wait0();
        __syncthreads();

        if (kb + BK < K) {
            uint32_t d = sb + (st ^ 1) * STAGE_B + sto;
            const int ko = kb + BK;
            cp_async16(d + ST_AH, aHp + ko);  cp_async16(d + ST_AH + 16, (const char*)(aHp + ko) + 16);
            cp_async16(d + ST_AL, aLp + ko);  cp_async16(d + ST_AL + 16, (const char*)(aLp + ko) + 16);
            cp_async16(d + ST_BH, bHp + ko);  cp_async16(d + ST_BH + 16, (const char*)(bHp + ko) + 16);
            cp_async16(d + ST_BL, bLp + ko);  cp_async16(d + ST_BL + 16, (const char*)(bLp + ko) + 16);
            cp_commit();
        }

        const uint32_t stb = (uint32_t)(st * STAGE_B);
        #pragma unroll
        for (int ks = 0; ks < 2; ks++) {
            const uint32_t kb2 = (uint32_t)(ks * 16) * 2;
            uint32_t aH[2][4], aL[2][4], b[4][4];
            #pragma unroll
            for (int t = 0; t < 2; t++) {
                ldsm_x4(aH[t], aBase + stb + ST_AH + (uint32_t)(t * 16 * LDA) * 2 + kb2);
                ldsm_x4(aL[t], aBase + stb + ST_AL + (uint32_t)(t * 16 * LDA) * 2 + kb2);
            }
            #pragma unroll
            for (int np = 0; np < 4; np++)
                ldsm_x4(b[np], bBase + stb + ST_BH + (uint32_t)(np * 16 * LDA) * 2 + kb2);
            #pragma unroll
            for (int t = 0; t < 2; t++)
                #pragma unroll
                for (int nt = 0; nt < 8; nt++)
                    mma16816(acc[t][nt], aH[t], &b[nt >> 1][(nt & 1) * 2]);
            #pragma unroll
            for (int t = 0; t < 2; t++)
                #pragma unroll
                for (int nt = 0; nt < 8; nt++)
                    mma16816(acc[t][nt], aL[t], &b[nt >> 1][(nt & 1) * 2]);
            #pragma unroll
            for (int np = 0; np < 4; np++)
                ldsm_x4(b[np], bBase + stb + ST_BL + (uint32_t)(np * 16 * LDA) * 2 + kb2);
            #pragma unroll
            for (int t = 0; t < 2; t++)
                #pragma unroll
                for (int nt = 0; nt < 8; nt++)
                    mma16816(acc[t][nt], aH[t], &b[nt >> 1][(nt & 1) * 2]);
        }
        st ^= 1;
        __syncthreads();
    }

    const int g = lane >> 2, tig = lane & 3;
    #pragma unroll
    for (int t = 0; t < 2; t++) {
        const int row = m0 + wm * 32 + t * 16 + g;
        #pragma unroll
        for (int nt = 0; nt < 8; nt++) {
            const int col = n0 + wn * 64 + nt * 8 + tig * 2;
            if (SPLIT_OUT) {
                uint32_t hp0, lp0, hp1, lp1;
                split2(acc[t][nt][0], acc[t][nt][1], hp0, lp0);
                split2(acc[t][nt][2], acc[t][nt][3], hp1, lp1);
                *(uint32_t*)(Chi + (size_t)row * Ntot + col)        = hp0;
                *(uint32_t*)(Clo + (size_t)row * Ntot + col)        = lp0;
                *(uint32_t*)(Chi + (size_t)(row + 8) * Ntot + col)  = hp1;
                *(uint32_t*)(Clo + (size_t)(row + 8) * Ntot + col)  = lp1;
            } else {
                *(float2*)(C + (size_t)row * Ntot + col) =
                    make_float2(acc[t][nt][0], acc[t][nt][1]);
                *(float2*)(C + (size_t)(row + 8) * Ntot + col) =
                    make_float2(acc[t][nt][2], acc[t][nt][3]);
            }
        }
    }
}

__global__ __launch_bounds__(256)
void qkv_mma()
{
    const __nv_bfloat16 *Bh, *Bl;
    __nv_bfloat16 *Oh, *Ol;
    if (blockIdx.z == 0)      { Bh = g_Wqh; Bl = g_Wql; Oh = g_Qh; Ol = g_Ql; }
    else if (blockIdx.z == 1) { Bh = g_Wkh; Bl = g_Wkl; Oh = g_Kh; Ol = g_Kl; }
    else                      { Bh = g_Wvh; Bl = g_Wvl; Oh = g_Vh; Ol = g_Vl; }
    gemm_bf16split<true>(g_Xh, g_Xl, Bh, Bl, nullptr, Oh, Ol, DMODEL, DMODEL);
}

__global__ __launch_bounds__(256)
void out_mma(float* __restrict__ Out)
{
    gemm_bf16split<false>(g_Ch, g_Cl, g_Woh, g_Wol, Out, nullptr, nullptr,
                          DMODEL, DMODEL);
}

// ---------------------------------------------------------------------------
// HMMA flash attention.  Block = 64 q-rows (4 warps, m16 each), 64-key tiles.
// S = QhKh + QlKh + QhKl; online softmax on c-frags; P split in regs;
// O += PhVh + PlVh + PhVl (V via ldmatrix.trans).
// ---------------------------------------------------------------------------
#define LDV 72
#define TQK (64 * LDV * 2)       // 9216 B per tile
#define AQ_H 0
#define AQ_L (1 * TQK)
#define AK_H (2 * TQK)
#define AK_L (3 * TQK)
#define AV_H (4 * TQK)
#define AV_L (5 * TQK)
#define ATT_SMEM (6 * TQK)       // 55296 B

__global__ __launch_bounds__(128)
void attn_mma()
{
    extern __shared__ char smb[];
    const uint32_t sb = smem_to_u32(smb);
    const int tid  = threadIdx.x;
    const int w    = tid >> 5;
    const int lane = tid & 31;
    const int qt = blockIdx.x, h = blockIdx.y, b = blockIdx.z;
    const int q0 = qt * 64;
    const size_t base = (size_t)b * SEQ * DMODEL + (size_t)h * DKH;

    // Loader mapping: row = tid>>1, 32 elems (64B = 4x16B) per thread
    const int lrow = tid >> 1;
    const int lcs  = (tid & 1) * 32;
    const uint32_t sdst = sb + (uint32_t)(lrow * LDV + lcs) * 2;

    // Load Q tile (hi/lo)
    {
        const __nv_bfloat16* qh = g_Qh + base + (size_t)(q0 + lrow) * DMODEL + lcs;
        const __nv_bfloat16* ql = g_Ql + base + (size_t)(q0 + lrow) * DMODEL + lcs;
        #pragma unroll
        for (int c = 0; c < 4; c++) {
            cp_async16(sdst + AQ_H + c * 16, (const char*)qh + c * 16);
            cp_async16(sdst + AQ_L + c * 16, (const char*)ql + c * 16);
        }
        cp_commit();
    }

    // Fragment addressing
    const int a_row  = lane & 15;
    const int a_koff = (lane & 16) >> 1;
    const uint32_t aQ = sb + (uint32_t)((w * 16 + a_row) * LDV + a_koff) * 2;
    const int b_row  = ((lane & 16) >> 1) + (lane & 7);
    const int b_koff = (lane & 8);
    const uint32_t aK = sb + (uint32_t)(b_row * LDV + b_koff) * 2;
    const int v_key = lane & 15;
    const int v_d   = (lane >> 4) * 8;
    const uint32_t aV = sb + (uint32_t)(v_key * LDV + v_d) * 2;

    cp_wait0();
    __syncthreads();

    // Q a-frags resident in registers
    uint32_t qah[4][4], qal[4][4];
    #pragma unroll
    for (int kk = 0; kk < 4; kk++) {
        ldsm_x4(qah[kk], aQ + AQ_H + (uint32_t)(kk * 16) * 2);
        ldsm_x4(qal[kk], aQ + AQ_L + (uint32_t)(kk * 16) * 2);
    }

    float O[8][4];
    #pragma unroll
    for (int j = 0; j < 8; j++)
        #pragma unroll
        for (int c = 0; c < 4; c++) O[j][c] = 0.0f;
    float m0 = -1e30f, m1 = -1e30f, L0 = 0.0f, L1 = 0.0f;

    for (int kt = 0; kt < SEQ / 64; kt++) {
        // Load K/V tiles (hi/lo)
        {
            const size_t roff = base + (size_t)(kt * 64 + lrow) * DMODEL + lcs;
            const __nv_bfloat16* kh = g_Kh + roff;
            const __nv_bfloat16* kl = g_Kl + roff;
            const __nv_bfloat16* vh = g_Vh + roff;
            const __nv_bfloat16* vl = g_Vl + roff;
            #pragma unroll
            for (int c = 0; c < 4; c++) {
                cp_async16(sdst + AK_H + c * 16, (const char*)kh + c * 16);
                cp_async16(sdst + AK_L + c * 16, (const char*)kl + c * 16);
                cp_async16(sdst + AV_H + c * 16, (const char*)vh + c * 16);
                cp_async16(sdst + AV_L + c * 16, (const char*)vl + c * 16);
            }
            cp_commit();
        }
        cp_wait0();
        __syncthreads();

        // S = Q K^T  (3-term split)
        float s[8][4];
        #pragma unroll
        for (int j = 0; j < 8; j++)
            #pragma unroll
            for (int c = 0; c < 4; c++) s[j][c] = 0.0f;

        #pragma unroll
        for (int kk = 0; kk < 4; kk++) {
            uint32_t kbh[4][4], kbl[4][4];
            #pragma unroll
            for (int np = 0; np < 4; np++) {
                ldsm_x4(kbh[np], aK + AK_H + (uint32_t)(np * 16 * LDV + kk * 16) * 2);
                ldsm_x4(kbl[np], aK + AK_L + (uint32_t)(np * 16 * LDV + kk * 16) * 2);
            }
            #pragma unroll
            for (int nt = 0; nt < 8; nt++) {
                mma16816(s[nt], qah[kk], &kbh[nt >> 1][(nt & 1) * 2]);
                mma16816(s[nt], qal[kk], &kbh[nt >> 1][(nt & 1) * 2]);
                mma16816(s[nt], qah[kk], &kbl[nt >> 1][(nt & 1) * 2]);
            }
        }

        // Online softmax (rows r = lane>>2 and r+8; reduce over quad lanes)
        float mx0 = -1e30f, mx1 = -1e30f;
        #pragma unroll
        for (int j = 0; j < 8; j++) {
            mx0 = fmaxf(mx0, fmaxf(s[j][0], s[j][1]));
            mx1 = fmaxf(mx1, fmaxf(s[j][2], s[j][3]));
        }
        mx0 = fmaxf(mx0, __shfl_xor_sync(0xffffffffu, mx0, 1));
        mx0 = fmaxf(mx0, __shfl_xor_sync(0xffffffffu, mx0, 2));
        mx1 = fmaxf(mx1, __shfl_xor_sync(0xffffffffu, mx1, 1));
        mx1 = fmaxf(mx1, __shfl_xor_sync(0xffffffffu, mx1, 2));

        const float mn0 = fmaxf(m0, mx0), mn1 = fmaxf(m1, mx1);
        const float cr0 = ex2f((m0 - mn0) * SL);
        const float cr1 = ex2f((m1 - mn1) * SL);
        m0 = mn0; m1 = mn1;
        const float msl0 = mn0 * SL, msl1 = mn1 * SL;

        float rs0 = 0.0f, rs1 = 0.0f;
        #pragma unroll
        for (int j = 0; j < 8; j++) {
            s[j][0] = ex2f(fmaf(s[j][0], SL, -msl0));
            s[j][1] = ex2f(fmaf(s[j][1], SL, -msl0));
            s[j][2] = ex2f(fmaf(s[j][2], SL, -msl1));
            s[j][3] = ex2f(fmaf(s[j][3], SL, -msl1));
            rs0 += s[j][0] + s[j][1];
            rs1 += s[j][2] + s[j][3];
        }
        rs0 += __shfl_xor_sync(0xffffffffu, rs0, 1);
        rs0 += __shfl_xor_sync(0xffffffffu, rs0, 2);
        rs1 += __shfl_xor_sync(0xffffffffu, rs1, 1);
        rs1 += __shfl_xor_sync(0xffffffffu, rs1, 2);
        L0 = L0 * cr0 + rs0;
        L1 = L1 * cr1 + rs1;

        #pragma unroll
        for (int j = 0; j < 8; j++) {
            O[j][0] *= cr0; O[j][1] *= cr0;
            O[j][2] *= cr1; O[j][3] *= cr1;
        }

        // O += P V  (3-term split; P packed from s-frags in registers)
        #pragma unroll
        for (int kk = 0; kk < 4; kk++) {
            uint32_t pah[4], pal[4];
            split2(s[2 * kk][0],     s[2 * kk][1],     pah[0], pal[0]);
            split2(s[2 * kk][2],     s[2 * kk][3],     pah[1], pal[1]);
            split2(s[2 * kk + 1][0], s[2 * kk + 1][1], pah[2], pal[2]);
            split2(s[2 * kk + 1][2], s[2 * kk + 1][3], pah[3], pal[3]);
            #pragma unroll
            for (int dt = 0; dt < 4; dt++) {
                uint32_t vbh[4], vbl[4];
                const uint32_t vo = (uint32_t)(kk * 16 * LDV + dt * 16) * 2;
                ldsm_x4t(vbh, aV + AV_H + vo);
                ldsm_x4t(vbl, aV + AV_L + vo);
                mma16816(O[2 * dt],     pah, &vbh[0]);
                mma16816(O[2 * dt + 1], pah, &vbh[2]);
                mma16816(O[2 * dt],     pal, &vbh[0]);
                mma16816(O[2 * dt + 1], pal, &vbh[2]);
                mma16816(O[2 * dt],     pah, &vbl[0]);
                mma16816(O[2 * dt + 1], pah, &vbl[2]);
            }
        }
        __syncthreads();
    }

    // Epilogue: normalize, split-bf16 ctx
    const float inv0 = 1.0f / L0, inv1 = 1.0f / L1;
    const int g = lane >> 2, tig = lane & 3;
    const int row0 = q0 + w * 16 + g;
    #pragma unroll
    for (int j = 0; j < 8; j++) {
        const int col = j * 8 + tig * 2;
        uint32_t hp0, lp0, hp1, lp1;
        split2(O[j][0] * inv0, O[j][1] * inv0, hp0, lp0);
        split2(O[j][2] * inv1, O[j][3] * inv1, hp1, lp1);
        *(uint32_t*)(g_Ch + base + (size_t)row0 * DMODEL + col)       = hp0;
        *(uint32_t*)(g_Cl + base + (size_t)row0 * DMODEL + col)       = lp0;
        *(uint32_t*)(g_Ch + base + (size_t)(row0 + 8) * DMODEL + col) = hp1;
        *(uint32_t*)(g_Cl + base + (size_t)(row0 + 8) * DMODEL + col) = lp1;
    }
}

// ---------------------------------------------------------------------------
extern "C" void kernel_launch(void* const* d_in, const int* in_sizes, int n_in,
                              void* d_out, int out_size)
{
    (void)in_sizes; (void)n_in; (void)out_size;
    const float* emb = (const float*)d_in[0];
    const float* Wq  = (const float*)d_in[1];
    const float* Wk  = (const float*)d_in[2];
    const float* Wv  = (const float*)d_in[3];
    const float* Wo  = (const float*)d_in[4];
    float* out = (float*)d_out;

    dim3 gsplit(ROWS * DMODEL / 4 / 256, 1, 5);
    split_all<<<gsplit, 256>>>(emb, Wq, Wk, Wv, Wo);

    cudaFuncSetAttribute(qkv_mma, cudaFuncAttributeMaxDynamicSharedMemorySize,
                         GS_TOTAL);
    dim3 g1(DMODEL / 128, ROWS / 128, 3);
    qkv_mma<<<g1, 256, GS_TOTAL>>>();

    cudaFuncSetAttribute(attn_mma, cudaFuncAttributeMaxDynamicSharedMemorySize,
                         ATT_SMEM);
    dim3 g2(SEQ / 64, NHEAD, BATCH);
    attn_mma<<<g2, 128, ATT_SMEM>>>();

    cudaFuncSetAttribute(out_mma, cudaFuncAttributeMaxDynamicSharedMemorySize,
                         GS_TOTAL);
    dim3 g3(DMODEL / 128, ROWS / 128, 1);
    out_mma<<<g3, 256, GS_TOTAL>>>(out);
}